// round 12
// baseline (speedup 1.0000x reference)
#include <cuda_runtime.h>
#include <cuda_fp16.h>

#define N_NODES  100000
#define N_EDGES  3200000
#define N_GRAPHS 256
#define HID      32
#define IN_DIM   6
#define BN_EPS   1e-5f
#define FULL     0xffffffffu
#define MAXGRID  2048

// ---------------- device scratch (no allocations allowed) ----------------
__device__ __align__(16) int2 g_edge[N_EDGES];   // CSR: {srow, ew_as_int}, sorted by col
__device__ __align__(16) uint4 g_posh[N_NODES];  // fp16-packed pos row
__device__ float g_dinv[N_NODES];
__device__ int   g_cnt[N_NODES];
__device__ int   g_start[N_NODES];
__device__ int   g_cursor[N_NODES];
__device__ int   g_bsum[MAXGRID];
__device__ int   g_boff[MAXGRID];
__device__ __align__(16) float g_yA[N_NODES * HID];  // y = dinv * xw
__device__ __align__(16) float g_yB[N_NODES * HID];
__device__ float g_sums[N_GRAPHS * HID];
__device__ int   g_cnts[N_GRAPHS];
__device__ unsigned g_bar_count;   // zero-init; self-resetting
__device__ unsigned g_bar_phase;   // monotonic across replays

struct SMem {
    union {
        int scan[256];
        struct {
            float Ws[HID * HID];
            int2  e[8][32];
            float h[8][32];
        } g;
    };
};

// software grid barrier: monotonic phase counter (no sense reversal needed)
__device__ __forceinline__ void grid_sync(unsigned target) {
    __syncthreads();
    if (threadIdx.x == 0) {
        __threadfence();
        unsigned old = atomicAdd(&g_bar_count, 1u);
        if (old == gridDim.x - 1) {
            g_bar_count = 0;           // reset BEFORE release
            __threadfence();
            atomicExch(&g_bar_phase, target);
        } else {
            while (atomicAdd(&g_bar_phase, 0u) < target) __nanosleep(64);
        }
        __threadfence();
    }
    __syncthreads();
}

// R5-structure gather layer: warp/node, float4 groups (4 edges/iter), folded dinv.
__device__ __forceinline__ void gather_layer(
    SMem* sm, const float* __restrict__ y, float* __restrict__ yout,
    const float* __restrict__ b,
    const float* __restrict__ bng, const float* __restrict__ bnb,
    const float* __restrict__ Wnext,
    float* __restrict__ emb, const int* __restrict__ batch,
    int warp, int lane, int gwarp, int nwarps)
{
    if (Wnext) {
        for (int i = threadIdx.x; i < HID * HID; i += blockDim.x) sm->g.Ws[i] = Wnext[i];
    }
    __syncthreads();
    const float4* y4 = (const float4*)y;
    int grp = lane >> 3;
    int sub = lane & 7;

    for (int n = gwarp; n < N_NODES; n += nwarps) {
        int start = g_start[n];
        int cnt   = g_cnt[n];
        int end   = start + cnt;
        float4 acc = make_float4(0.f, 0.f, 0.f, 0.f);

        for (int base = start; base < end; base += 32) {
            int m = end - base; if (m > 32) m = 32;
            if (lane < m) sm->g.e[warp][lane] = __ldg(&g_edge[base + lane]);
            __syncwarp();
            int iters = (m + 3) >> 2;
            for (int j = 0; j < iters; ++j) {
                int eidx = j * 4 + grp;
                int  sel = eidx < m ? eidx : m - 1;
                int2 e   = sm->g.e[warp][sel];
                float w  = (eidx < m) ? __int_as_float(e.y) : 0.f;
                float4 v = __ldg(&y4[(size_t)e.x * 8 + sub]);
                acc.x = fmaf(w, v.x, acc.x);
                acc.y = fmaf(w, v.y, acc.y);
                acc.z = fmaf(w, v.z, acc.z);
                acc.w = fmaf(w, v.w, acc.w);
            }
            __syncwarp();
        }

        #pragma unroll
        for (int off = 8; off < 32; off <<= 1) {
            acc.x += __shfl_xor_sync(FULL, acc.x, off);
            acc.y += __shfl_xor_sync(FULL, acc.y, off);
            acc.z += __shfl_xor_sync(FULL, acc.z, off);
            acc.w += __shfl_xor_sync(FULL, acc.w, off);
        }

        float di = g_dinv[n];
        // conv = b + di*(y_self + S)
        {
            float4 ys = __ldg(&y4[(size_t)n * 8 + sub]);
            float4 bb = __ldg(&((const float4*)b)[sub]);
            acc.x = fmaf(di, acc.x + ys.x, bb.x);
            acc.y = fmaf(di, acc.y + ys.y, bb.y);
            acc.z = fmaf(di, acc.z + ys.z, bb.z);
            acc.w = fmaf(di, acc.w + ys.w, bb.w);
        }

        if (grp == 0) ((float4*)&sm->g.h[warp][0])[sub] = acc;
        __syncwarp();
        float aS = sm->g.h[warp][lane];

        if (Wnext) {
            float sc = bng[lane] * rsqrtf(1.0f + BN_EPS);
            float h  = fmaxf(fmaf(aS, sc, bnb[lane]), 0.f);
            float o  = 0.f;
            #pragma unroll
            for (int k = 0; k < HID; ++k)
                o = fmaf(__shfl_sync(FULL, h, k), sm->g.Ws[k * HID + lane], o);
            yout[(size_t)n * HID + lane] = di * o;
        } else {
            emb[(size_t)n * HID + lane] = aS;
            int gidx = batch[n];
            atomicAdd(&g_sums[(size_t)gidx * HID + lane], aS);
            if (lane == 0) atomicAdd(&g_cnts[gidx], 1);
        }
    }
}

__global__ void __launch_bounds__(256)
k_fused(const float* __restrict__ x, const int* __restrict__ ei,
        const float* __restrict__ pos, const int* __restrict__ batch,
        const float* __restrict__ ps1, const float* __restrict__ ps2,
        const float* __restrict__ W1, const float* __restrict__ b1,
        const float* __restrict__ W2, const float* __restrict__ b2,
        const float* __restrict__ W3, const float* __restrict__ b3,
        const float* __restrict__ W4, const float* __restrict__ b4,
        const float* __restrict__ g1, const float* __restrict__ be1,
        const float* __restrict__ g2, const float* __restrict__ be2,
        const float* __restrict__ g3, const float* __restrict__ be3,
        const float* __restrict__ Wout, const float* __restrict__ bout,
        float* __restrict__ emb, float* __restrict__ pred)
{
    __shared__ SMem sm;
    const int tid    = threadIdx.x;
    const int bid    = blockIdx.x;
    const int ngrid  = gridDim.x;
    const int nthr   = ngrid * 256;
    const int gtid   = bid * 256 + tid;
    const int warp   = tid >> 5;
    const int lane   = tid & 31;
    const int gwarp  = gtid >> 5;
    const int nwarps = nthr >> 5;

    const unsigned base = atomicAdd(&g_bar_phase, 0u);  // stable pre-barrier

    // ---- P0: init (zero cnt/sums/cnts, pack pos fp16) ----
    for (int i = gtid; i < N_NODES; i += nthr) {
        g_cnt[i] = 0;
        const float2* p2 = (const float2*)(pos + (size_t)i * 6);
        float2 a = p2[0], b = p2[1], c = p2[2];
        __half2 h0 = __floats2half2_rn(a.x, a.y);
        __half2 h1 = __floats2half2_rn(b.x, b.y);
        __half2 h2 = __floats2half2_rn(c.x, c.y);
        uint4 u;
        u.x = *(const unsigned*)&h0;
        u.y = *(const unsigned*)&h1;
        u.z = *(const unsigned*)&h2;
        u.w = 0u;
        g_posh[i] = u;
    }
    for (int i = gtid; i < N_GRAPHS * HID; i += nthr) g_sums[i] = 0.f;
    for (int i = gtid; i < N_GRAPHS; i += nthr)       g_cnts[i] = 0;
    grid_sync(base + 1);

    // ---- P1: in-degree histogram (int4 cols) ----
    {
        const int4* col4 = (const int4*)(ei + N_EDGES);
        for (int q = gtid; q < N_EDGES / 4; q += nthr) {
            int4 c = __ldg(&col4[q]);
            atomicAdd(&g_cnt[c.x], 1);
            atomicAdd(&g_cnt[c.y], 1);
            atomicAdd(&g_cnt[c.z], 1);
            atomicAdd(&g_cnt[c.w], 1);
        }
    }
    grid_sync(base + 2);

    // ---- P2: scan A — per-block chunk sums ----
    const int CH = (N_NODES + ngrid - 1) / ngrid;
    const int PT = (CH + 255) / 256;
    const int lo = bid * CH;
    const int hi = min(lo + CH, N_NODES);
    const int tb = lo + tid * PT;
    {
        int s = 0;
        for (int i = 0; i < PT; ++i) {
            int idx = tb + i;
            if (idx < hi) s += g_cnt[idx];
        }
        sm.scan[tid] = s;
        __syncthreads();
        #pragma unroll
        for (int off = 128; off > 0; off >>= 1) {
            if (tid < off) sm.scan[tid] += sm.scan[tid + off];
            __syncthreads();
        }
        if (tid == 0) g_bsum[bid] = sm.scan[0];
    }
    grid_sync(base + 3);

    // ---- P3: scan B — block 0 exclusive-scans the ngrid partials ----
    if (bid == 0) {
        int K = (ngrid + 255) / 256;
        int b0 = tid * K;
        int s = 0;
        for (int i = 0; i < K; ++i) {
            int idx = b0 + i;
            if (idx < ngrid) s += g_bsum[idx];
        }
        sm.scan[tid] = s;
        __syncthreads();
        #pragma unroll
        for (int off = 1; off < 256; off <<= 1) {
            int add = (tid >= off) ? sm.scan[tid - off] : 0;
            __syncthreads();
            sm.scan[tid] += add;
            __syncthreads();
        }
        int run = (tid == 0) ? 0 : sm.scan[tid - 1];
        for (int i = 0; i < K; ++i) {
            int idx = b0 + i;
            if (idx < ngrid) {
                g_boff[idx] = run;
                run += g_bsum[idx];
            }
        }
    }
    grid_sync(base + 4);

    // ---- P4: scan C — local exclusive scan + global offset ----
    {
        int v[8];  // PT <= 8 for ngrid >= 49 (occupancy sizing guarantees far more)
        int s = 0;
        for (int i = 0; i < PT; ++i) {
            int idx = tb + i;
            v[i] = (idx < hi) ? g_cnt[idx] : 0;
            s += v[i];
        }
        sm.scan[tid] = s;
        __syncthreads();
        #pragma unroll
        for (int off = 1; off < 256; off <<= 1) {
            int add = (tid >= off) ? sm.scan[tid - off] : 0;
            __syncthreads();
            sm.scan[tid] += add;
            __syncthreads();
        }
        int run = g_boff[bid] + ((tid == 0) ? 0 : sm.scan[tid - 1]);
        for (int i = 0; i < PT; ++i) {
            int idx = tb + i;
            if (idx < hi) {
                g_start[idx]  = run;
                g_cursor[idx] = run;
                run += v[i];
            }
        }
    }
    grid_sync(base + 5);

    // ---- P5: edge weight + bucket scatter ----
    {
        const int* row = ei;
        const int* col = ei + N_EDGES;
        float s1 = ps1[0], s2 = ps2[0];
        float s1sq = s1 * s1, s2sq = s2 * s2;
        for (int e = gtid; e < N_EDGES; e += nthr) {
            int r = row[e];
            int c = col[e];
            uint4 ur = __ldg(&g_posh[r]);
            uint4 uc = __ldg(&g_posh[c]);
            float2 r0 = __half22float2(*(const __half2*)&ur.x);
            float2 r1 = __half22float2(*(const __half2*)&ur.y);
            float2 r2 = __half22float2(*(const __half2*)&ur.z);
            float2 c0 = __half22float2(*(const __half2*)&uc.x);
            float2 c1 = __half22float2(*(const __half2*)&uc.y);
            float2 c2 = __half22float2(*(const __half2*)&uc.z);
            float d0 = r0.x - c0.x;
            float d1 = r0.y - c0.y;
            float d2 = r1.x - c1.x;
            float D  = d0 * d0 + d1 * d1 + d2 * d2;
            float dot = r1.y * c1.y + r2.x * c2.x + r2.y * c2.y;
            float t  = 1.0f - dot;
            float w  = __expf(-(D * s1sq + t * t * s2sq));
            int p = atomicAdd(&g_cursor[c], 1);
            g_edge[p] = make_int2(r, __float_as_int(w));
        }
    }
    grid_sync(base + 6);

    // ---- P6: degsum (CSR segment sum) + dinv + layer-1 GEMM, fused per node ----
    {
        for (int i = tid; i < IN_DIM * HID; i += 256) sm.g.Ws[i] = W1[i];
        __syncthreads();
        for (int n = gwarp; n < N_NODES; n += nwarps) {
            int start = g_start[n];
            int end   = start + g_cnt[n];
            float s = 0.f;
            for (int j = start + lane; j < end; j += 32)
                s += __int_as_float(__ldg(&g_edge[j]).y);
            #pragma unroll
            for (int off = 16; off > 0; off >>= 1)
                s += __shfl_xor_sync(FULL, s, off);
            float di = rsqrtf(s + 1.0f);
            if (lane == 0) g_dinv[n] = di;
            float hv = (lane < IN_DIM) ? x[(size_t)n * IN_DIM + lane] : 0.f;
            float acc = 0.f;
            #pragma unroll
            for (int k = 0; k < IN_DIM; ++k)
                acc = fmaf(__shfl_sync(FULL, hv, k), sm.g.Ws[k * HID + lane], acc);
            g_yA[(size_t)n * HID + lane] = di * acc;
        }
    }
    grid_sync(base + 7);

    // ---- P7..P10: four gather layers ----
    gather_layer(&sm, g_yA, g_yB, b1, g1, be1, W2, nullptr, nullptr, warp, lane, gwarp, nwarps);
    grid_sync(base + 8);
    gather_layer(&sm, g_yB, g_yA, b2, g2, be2, W3, nullptr, nullptr, warp, lane, gwarp, nwarps);
    grid_sync(base + 9);
    gather_layer(&sm, g_yA, g_yB, b3, g3, be3, W4, nullptr, nullptr, warp, lane, gwarp, nwarps);
    grid_sync(base + 10);
    gather_layer(&sm, g_yB, nullptr, b4, nullptr, nullptr, nullptr, emb, batch, warp, lane, gwarp, nwarps);
    grid_sync(base + 11);

    // ---- P11: prediction head (block 0) ----
    if (bid == 0 && tid < N_GRAPHS) {
        float cnt = fmaxf((float)g_cnts[tid], 1.0f);
        float inv = 1.0f / cnt;
        float acc = bout[0];
        #pragma unroll
        for (int k = 0; k < HID; ++k)
            acc = fmaf(g_sums[tid * HID + k] * inv, Wout[k], acc);
        pred[tid] = 1.0f / (1.0f + expf(-acc));
    }
}

// ---------------- launcher ----------------
extern "C" void kernel_launch(void* const* d_in, const int* in_sizes, int n_in,
                              void* d_out, int out_size) {
    const float* x     = (const float*)d_in[0];
    const int*   ei    = (const int*)  d_in[1];
    const float* pos   = (const float*)d_in[2];
    const int*   batch = (const int*)  d_in[3];
    const float* s1    = (const float*)d_in[4];
    const float* s2    = (const float*)d_in[5];
    const float* W1 = (const float*)d_in[6];
    const float* b1 = (const float*)d_in[7];
    const float* W2 = (const float*)d_in[8];
    const float* b2 = (const float*)d_in[9];
    const float* W3 = (const float*)d_in[10];
    const float* b3 = (const float*)d_in[11];
    const float* W4 = (const float*)d_in[12];
    const float* b4 = (const float*)d_in[13];
    const float* g1 = (const float*)d_in[14];
    const float* be1= (const float*)d_in[15];
    const float* g2 = (const float*)d_in[16];
    const float* be2= (const float*)d_in[17];
    const float* g3 = (const float*)d_in[18];
    const float* be3= (const float*)d_in[19];
    const float* Wout = (const float*)d_in[20];
    const float* bout = (const float*)d_in[21];

    float* outp = (float*)d_out;
    float* emb  = outp;                           // [N_NODES, HID]
    float* pred = outp + (size_t)N_NODES * HID;   // [N_GRAPHS]

    // size grid for guaranteed co-residency (software grid barrier)
    int dev = 0;
    cudaGetDevice(&dev);
    int sms = 0;
    cudaDeviceGetAttribute(&sms, cudaDevAttrMultiProcessorCount, dev);
    int nb = 0;
    cudaOccupancyMaxActiveBlocksPerMultiprocessor(&nb, k_fused, 256, 0);
    int grid = sms * nb;
    if (grid > MAXGRID) grid = MAXGRID;
    if (grid < 1) grid = 1;

    k_fused<<<grid, 256>>>(x, ei, pos, batch, s1, s2,
                           W1, b1, W2, b2, W3, b3, W4, b4,
                           g1, be1, g2, be2, g3, be3,
                           Wout, bout, emb, pred);
}

// round 13
// speedup vs baseline: 1.6038x; 1.6038x over previous
#include <cuda_runtime.h>
#include <cuda_fp16.h>

#define N_NODES  100000
#define N_EDGES  3200000
#define N_GRAPHS 256
#define HID      32
#define IN_DIM   6
#define BN_EPS   1e-5f
#define FULL     0xffffffffu

#define SCAN_BLOCKS 125
#define SCAN_CHUNK  800
#define SCAN_T      256
#define SCAN_PT     4

// ---------------- device scratch (no allocations allowed) ----------------
__device__ __align__(16) int2 g_edge[N_EDGES];   // CSR: {srow, ew_as_int}, sorted by col
__device__ __align__(16) uint4 g_posh[N_NODES];  // fp16-packed pos row
__device__ float g_dinv[N_NODES];
__device__ int   g_cnt[N_NODES];
__device__ int   g_start[N_NODES];
__device__ int   g_cursor[N_NODES];
__device__ int   g_bsum[SCAN_BLOCKS];
__device__ int   g_boff[SCAN_BLOCKS];
__device__ __align__(16) float g_yA[N_NODES * HID];  // y = dinv * xw (fp32)
__device__ __align__(16) float g_yB[N_NODES * HID];
__device__ float g_sums[N_GRAPHS * HID];
__device__ int   g_cnts[N_GRAPHS];

__device__ __forceinline__ const float* in_buf(int which)  { return which ? g_yB : g_yA; }
__device__ __forceinline__ float*       out_buf(int which) { return which ? g_yB : g_yA; }

// ---------------- kernels ----------------

// zero + pack pos into fp16 uint4 slots
__global__ void k_init(const float* __restrict__ pos) {
    int i = blockIdx.x * blockDim.x + threadIdx.x;
    if (i < N_NODES) {
        g_cnt[i] = 0;
        const float2* p2 = (const float2*)(pos + (size_t)i * 6);
        float2 a = p2[0], b = p2[1], c = p2[2];
        __half2 h0 = __floats2half2_rn(a.x, a.y);
        __half2 h1 = __floats2half2_rn(b.x, b.y);
        __half2 h2 = __floats2half2_rn(c.x, c.y);
        uint4 u;
        u.x = *(const unsigned*)&h0;
        u.y = *(const unsigned*)&h1;
        u.z = *(const unsigned*)&h2;
        u.w = 0u;
        g_posh[i] = u;
    }
    if (i < N_GRAPHS * HID) g_sums[i] = 0.f;
    if (i < N_GRAPHS)       g_cnts[i] = 0;
}

// in-degree histogram (REDG, no return). int4 col reads: 4 edges/lane/iter.
__global__ void k_hist(const int* __restrict__ ei) {
    const int4* col4 = (const int4*)(ei + N_EDGES);
    int stride = gridDim.x * blockDim.x;
    for (int q = blockIdx.x * blockDim.x + threadIdx.x; q < N_EDGES / 4; q += stride) {
        int4 c = __ldg(&col4[q]);
        atomicAdd(&g_cnt[c.x], 1);
        atomicAdd(&g_cnt[c.y], 1);
        atomicAdd(&g_cnt[c.z], 1);
        atomicAdd(&g_cnt[c.w], 1);
    }
}

// ---- 3-phase multi-block exclusive scan of g_cnt -> g_start / g_cursor ----
__global__ void k_scanA() {
    int blk = blockIdx.x, t = threadIdx.x;
    int lo = blk * SCAN_CHUNK;
    int base = lo + t * SCAN_PT;
    int s = 0;
    #pragma unroll
    for (int i = 0; i < SCAN_PT; ++i) {
        int idx = base + i;
        if (idx < lo + SCAN_CHUNK && idx < N_NODES) s += g_cnt[idx];
    }
    __shared__ int sh[SCAN_T];
    sh[t] = s;
    __syncthreads();
    #pragma unroll
    for (int off = SCAN_T / 2; off > 0; off >>= 1) {
        if (t < off) sh[t] += sh[t + off];
        __syncthreads();
    }
    if (t == 0) g_bsum[blk] = sh[0];
}

__global__ void k_scanB() {
    __shared__ int sh[SCAN_BLOCKS];
    int t = threadIdx.x;
    if (t < SCAN_BLOCKS) sh[t] = g_bsum[t];
    __syncthreads();
    if (t == 0) {
        int run = 0;
        for (int i = 0; i < SCAN_BLOCKS; ++i) {
            int v = sh[i];
            sh[i] = run;
            run += v;
        }
    }
    __syncthreads();
    if (t < SCAN_BLOCKS) g_boff[t] = sh[t];
}

__global__ void k_scanC() {
    int blk = blockIdx.x, t = threadIdx.x;
    int lo = blk * SCAN_CHUNK;
    int base = lo + t * SCAN_PT;
    int v[SCAN_PT];
    int s = 0;
    #pragma unroll
    for (int i = 0; i < SCAN_PT; ++i) {
        int idx = base + i;
        v[i] = (idx < lo + SCAN_CHUNK && idx < N_NODES) ? g_cnt[idx] : 0;
        s += v[i];
    }
    __shared__ int sh[SCAN_T];
    sh[t] = s;
    __syncthreads();
    #pragma unroll
    for (int off = 1; off < SCAN_T; off <<= 1) {
        int add = (t >= off) ? sh[t - off] : 0;
        __syncthreads();
        sh[t] += add;
        __syncthreads();
    }
    int run = g_boff[blk] + ((t == 0) ? 0 : sh[t - 1]);
    #pragma unroll
    for (int i = 0; i < SCAN_PT; ++i) {
        int idx = base + i;
        if (idx < lo + SCAN_CHUNK && idx < N_NODES) {
            g_start[idx]  = run;
            g_cursor[idx] = run;
            run += v[i];
        }
    }
}

// Edge weight + bucket-sort scatter. int4 edge-index loads: 4 edges per thread-iter.
__global__ void k_ewbuild(const int* __restrict__ ei,
                          const float* __restrict__ ps1,
                          const float* __restrict__ ps2) {
    const int4* row4 = (const int4*)ei;
    const int4* col4 = (const int4*)(ei + N_EDGES);
    float s1 = ps1[0], s2 = ps2[0];
    float s1sq = s1 * s1, s2sq = s2 * s2;
    int stride = gridDim.x * blockDim.x;
    for (int q = blockIdx.x * blockDim.x + threadIdx.x; q < N_EDGES / 4; q += stride) {
        int4 rr = __ldg(&row4[q]);
        int4 cc = __ldg(&col4[q]);
        int rs[4] = {rr.x, rr.y, rr.z, rr.w};
        int cs[4] = {cc.x, cc.y, cc.z, cc.w};
        #pragma unroll
        for (int k = 0; k < 4; ++k) {
            int r = rs[k], c = cs[k];
            uint4 ur = __ldg(&g_posh[r]);
            uint4 uc = __ldg(&g_posh[c]);
            float2 r0 = __half22float2(*(const __half2*)&ur.x);
            float2 r1 = __half22float2(*(const __half2*)&ur.y);
            float2 r2 = __half22float2(*(const __half2*)&ur.z);
            float2 c0 = __half22float2(*(const __half2*)&uc.x);
            float2 c1 = __half22float2(*(const __half2*)&uc.y);
            float2 c2 = __half22float2(*(const __half2*)&uc.z);
            float d0 = r0.x - c0.x;
            float d1 = r0.y - c0.y;
            float d2 = r1.x - c1.x;
            float D  = d0 * d0 + d1 * d1 + d2 * d2;
            float dot = r1.y * c1.y + r2.x * c2.x + r2.y * c2.y;
            float t  = 1.0f - dot;
            float w  = __expf(-(D * s1sq + t * t * s2sq));
            int p = atomicAdd(&g_cursor[c], 1);
            g_edge[p] = make_int2(r, __float_as_int(w));
        }
    }
}

// FUSED: deg segment-sum -> dinv -> layer-1 GEMM -> y1 = dinv*(x@W1). Warp per node.
__global__ void k_gemm1(const float* __restrict__ x, const float* __restrict__ W1) {
    __shared__ float Ws[IN_DIM * HID];
    for (int i = threadIdx.x; i < IN_DIM * HID; i += blockDim.x) Ws[i] = W1[i];
    __syncthreads();
    int n = (blockIdx.x * blockDim.x + threadIdx.x) >> 5;
    int lane = threadIdx.x & 31;
    if (n >= N_NODES) return;

    int start = g_start[n];
    int end   = start + g_cnt[n];
    float s = 0.f;
    for (int j = start + lane; j < end; j += 32)
        s += __int_as_float(__ldg(&g_edge[j]).y);
    #pragma unroll
    for (int off = 16; off > 0; off >>= 1)
        s += __shfl_xor_sync(FULL, s, off);
    float di = rsqrtf(s + 1.0f);
    if (lane == 0) g_dinv[n] = di;

    float hv = (lane < IN_DIM) ? x[(size_t)n * IN_DIM + lane] : 0.f;
    float acc = 0.f;
    #pragma unroll
    for (int k = 0; k < IN_DIM; ++k)
        acc = fmaf(__shfl_sync(FULL, hv, k), Ws[k * HID + lane], acc);
    g_yA[(size_t)n * HID + lane] = di * acc;
}

// Gather layer: S = sum ew * y[r]; conv = b + dinv[n]*(y[n] + S). (R11 structure)
template <int FUSE_NEXT>
__global__ void k_gather(int in_which, int out_which,
                         const float* __restrict__ b,
                         const float* __restrict__ bng,
                         const float* __restrict__ bnb,
                         const float* __restrict__ Wnext,
                         float* __restrict__ emb,
                         const int* __restrict__ batch) {
    __shared__ float Ws[HID * HID];
    __shared__ int2  sh_e[8][32];
    if (FUSE_NEXT) {
        for (int i = threadIdx.x; i < HID * HID; i += blockDim.x) Ws[i] = Wnext[i];
        __syncthreads();
    }
    const float* y = in_buf(in_which);

    int warp = threadIdx.x >> 5;
    int lane = threadIdx.x & 31;
    int n = (blockIdx.x * blockDim.x + threadIdx.x) >> 5;
    if (n >= N_NODES) return;

    int start = g_start[n];
    int cnt   = g_cnt[n];
    int nfull = cnt >> 5;
    int rem   = cnt & 31;

    float acc = 0.f;
    const int2* ep = g_edge + start;

    for (int t = 0; t < nfull; ++t) {
        sh_e[warp][lane] = __ldg(&ep[t * 32 + lane]);
        __syncwarp();
        #pragma unroll
        for (int j = 0; j < 32; ++j) {
            int2 e = sh_e[warp][j];
            acc = fmaf(__int_as_float(e.y), __ldg(&y[(size_t)e.x * HID + lane]), acc);
        }
        __syncwarp();
    }
    if (rem) {
        int tb = nfull << 5;
        if (lane < rem) sh_e[warp][lane] = __ldg(&ep[tb + lane]);
        __syncwarp();
        for (int j = 0; j < rem; ++j) {
            int2 e = sh_e[warp][j];
            acc = fmaf(__int_as_float(e.y), __ldg(&y[(size_t)e.x * HID + lane]), acc);
        }
    }

    float di = g_dinv[n];
    acc += __ldg(&y[(size_t)n * HID + lane]);
    float aS = fmaf(di, acc, b[lane]);

    if (FUSE_NEXT) {
        float sc = bng[lane] * rsqrtf(1.0f + BN_EPS);
        float h  = fmaxf(fmaf(aS, sc, bnb[lane]), 0.f);
        float o  = 0.f;
        #pragma unroll
        for (int k = 0; k < HID; ++k)
            o = fmaf(__shfl_sync(FULL, h, k), Ws[k * HID + lane], o);
        out_buf(out_which)[(size_t)n * HID + lane] = di * o;
    } else {
        emb[(size_t)n * HID + lane] = aS;
        int gidx = batch[n];
        atomicAdd(&g_sums[(size_t)gidx * HID + lane], aS);
        if (lane == 0) atomicAdd(&g_cnts[gidx], 1);
    }
}

__global__ void k_pred(const float* __restrict__ Wout,
                       const float* __restrict__ bout,
                       float* __restrict__ pred) {
    int gI = threadIdx.x;
    if (gI >= N_GRAPHS) return;
    float cnt = fmaxf((float)g_cnts[gI], 1.0f);
    float inv = 1.0f / cnt;
    float acc = bout[0];
    #pragma unroll
    for (int k = 0; k < HID; ++k)
        acc = fmaf(g_sums[gI * HID + k] * inv, Wout[k], acc);
    pred[gI] = 1.0f / (1.0f + expf(-acc));
}

// ---------------- launcher ----------------
extern "C" void kernel_launch(void* const* d_in, const int* in_sizes, int n_in,
                              void* d_out, int out_size) {
    const float* x     = (const float*)d_in[0];
    const int*   ei    = (const int*)  d_in[1];
    const float* pos   = (const float*)d_in[2];
    const int*   batch = (const int*)  d_in[3];
    const float* s1    = (const float*)d_in[4];
    const float* s2    = (const float*)d_in[5];
    const float* W1 = (const float*)d_in[6];
    const float* b1 = (const float*)d_in[7];
    const float* W2 = (const float*)d_in[8];
    const float* b2 = (const float*)d_in[9];
    const float* W3 = (const float*)d_in[10];
    const float* b3 = (const float*)d_in[11];
    const float* W4 = (const float*)d_in[12];
    const float* b4 = (const float*)d_in[13];
    const float* g1 = (const float*)d_in[14];
    const float* be1= (const float*)d_in[15];
    const float* g2 = (const float*)d_in[16];
    const float* be2= (const float*)d_in[17];
    const float* g3 = (const float*)d_in[18];
    const float* be3= (const float*)d_in[19];
    const float* Wout = (const float*)d_in[20];
    const float* bout = (const float*)d_in[21];

    float* outp = (float*)d_out;
    float* emb  = outp;                           // [N_NODES, HID]
    float* pred = outp + (size_t)N_NODES * HID;   // [N_GRAPHS]

    const int ZB = (N_NODES + 255) / 256;
    const int NODE_WARP_BLOCKS = (N_NODES * 32 + 255) / 256;

    k_init   <<<ZB, 256>>>(pos);
    k_hist   <<<1024, 256>>>(ei);
    k_scanA  <<<SCAN_BLOCKS, SCAN_T>>>();
    k_scanB  <<<1, 128>>>();
    k_scanC  <<<SCAN_BLOCKS, SCAN_T>>>();
    k_ewbuild<<<2048, 256>>>(ei, s1, s2);
    k_gemm1  <<<NODE_WARP_BLOCKS, 256>>>(x, W1);

    k_gather<1><<<NODE_WARP_BLOCKS, 256>>>(0, 1, b1, g1, be1, W2, nullptr, nullptr);
    k_gather<1><<<NODE_WARP_BLOCKS, 256>>>(1, 0, b2, g2, be2, W3, nullptr, nullptr);
    k_gather<1><<<NODE_WARP_BLOCKS, 256>>>(0, 1, b3, g3, be3, W4, nullptr, nullptr);
    k_gather<0><<<NODE_WARP_BLOCKS, 256>>>(1, 0, b4, nullptr, nullptr, nullptr, emb, batch);

    k_pred<<<1, 256>>>(Wout, bout, pred);
}